// round 8
// baseline (speedup 1.0000x reference)
#include <cuda_runtime.h>
#include <cstdint>

namespace {

constexpr int ROWS = 64;           // edges per CTA
constexpr int THREADS = 512;       // 16 warps
constexpr int BLKW = 132;          // words per A frag block (512B + 16B pad)
constexpr int A_OFF = 0;           // 4 mb x 32 kb blocks = 16896 floats
constexpr int P_OFF = 16896;       // 2240 params
constexpr int BSM_OFF = 19136;     // 64 batch ids
constexpr int SMF = 19200;
constexpr int SMEM_BYTES = SMF * 4;   // 76800 B

constexpr int Pb1 = 0, Pg1 = 256, Pt1 = 512, Pb2 = 768, Pg2 = 1024, Pt2 = 1280;
constexpr int Pb3 = 1536, PWw = 1600, Pbw = 1856, Pgw = 1984, Ptw = 2112;

// frag-packed tf32 weights: [kb][nb][64]; W1 48x32, W2 32x32, W3 32x8
constexpr int W2B = 98304, W3B = 163840;
__device__ float g_wt[180224];
__device__ int g_is64;

__device__ __forceinline__ float f2tf(float f) {
    unsigned u; asm("cvt.rna.tf32.f32 %0, %1;" : "=r"(u) : "f"(f));
    return __uint_as_float(u);
}
__device__ __forceinline__ void mma8(float* d, const unsigned* a, unsigned b0, unsigned b1) {
    asm volatile(
        "mma.sync.aligned.m16n8k8.row.col.f32.tf32.tf32.f32 "
        "{%0,%1,%2,%3},{%4,%5,%6,%7},{%8,%9},{%0,%1,%2,%3};\n"
        : "+f"(d[0]), "+f"(d[1]), "+f"(d[2]), "+f"(d[3])
        : "r"(a[0]), "r"(a[1]), "r"(a[2]), "r"(a[3]), "r"(b0), "r"(b1));
}
__device__ __forceinline__ int a_word(int mb, int kb) { return (mb * 32 + kb) * BLKW; }

template <int NT>
__device__ __forceinline__ void ldB(const float* __restrict__ Wb, int kb, int nbstride,
                                    int nb0, int lane, float2 (&br)[NT]) {
    const float* p = Wb + (size_t)kb * nbstride + nb0 * 64 + lane * 2;
#pragma unroll
    for (int nt = 0; nt < NT; nt++) br[nt] = *(const float2*)(p + nt * 64);
}

template <int NT>
__device__ __forceinline__ void kstep(const float* __restrict__ As, int mb0, int kb,
                                      int lane, const float2 (&br)[NT], float (&acc)[NT][4]) {
    unsigned a[4];
    float4 av = *(const float4*)(As + a_word(mb0, kb) + lane * 4);
    a[0] = __float_as_uint(av.x); a[1] = __float_as_uint(av.y);
    a[2] = __float_as_uint(av.z); a[3] = __float_as_uint(av.w);
#pragma unroll
    for (int nt = 0; nt < NT; nt++)
        mma8(acc[nt], a, __float_as_uint(br[nt].x), __float_as_uint(br[nt].y));
}

// Barrier-free GEMM: A frag-packed smem, B frag-packed gmem.
// Distance-2 register prefetch via 4 buffers, loop unrolled by 4 kb (no copies).
template <int NT>
__device__ __forceinline__ void gemm_ldg(
    const float* __restrict__ Wb, const int KB, const int nbstride,
    const float* __restrict__ As, float (&acc)[NT][4],
    const int mb0, const int nb0, const int lane)
{
    float2 bA[NT], bB[NT], bC[NT], bD[NT];
    ldB<NT>(Wb, 0, nbstride, nb0, lane, bA);
    ldB<NT>(Wb, 1, nbstride, nb0, lane, bB);
#pragma unroll 1
    for (int kb = 0; kb < KB; kb += 4) {
        ldB<NT>(Wb, kb + 2, nbstride, nb0, lane, bC);
        ldB<NT>(Wb, kb + 3, nbstride, nb0, lane, bD);
        kstep<NT>(As, mb0, kb,     lane, bA, acc);
        kstep<NT>(As, mb0, kb + 1, lane, bB, acc);
        const int kn = (kb + 4 < KB) ? kb + 4 : 0;   // clamped dummy on last iter
        ldB<NT>(Wb, kn,     nbstride, nb0, lane, bA);
        ldB<NT>(Wb, kn + 1, nbstride, nb0, lane, bB);
        kstep<NT>(As, mb0, kb + 2, lane, bC, acc);
        kstep<NT>(As, mb0, kb + 3, lane, bD, acc);
    }
}

// acc(+bias) -> frag-packed A region (raw fp32). MT=1.
template <int NT>
__device__ __forceinline__ void store_acc_frag(
    float* __restrict__ A, const float (&acc)[NT][4], const float* __restrict__ bias,
    int mb0, int nb0, int gid, int tig)
{
    const int base = gid * 16 + (tig & 1) * 8 + 2 * (tig >> 1);
#pragma unroll
    for (int nt = 0; nt < NT; nt++) {
        int c0 = (nb0 + nt) * 8 + 2 * tig;
        int w = a_word(mb0, nb0 + nt) + base;
        A[w]     = acc[nt][0] + bias[c0];
        A[w + 4] = acc[nt][1] + bias[c0 + 1];
        A[w + 1] = acc[nt][2] + bias[c0];
        A[w + 5] = acc[nt][3] + bias[c0 + 1];
    }
}

// in-place LN+ReLU over 256-wide rows; 16 warps x 4 rows; writes tf32
__device__ __forceinline__ void ln_relu_frag(
    float* __restrict__ A, const float* __restrict__ g, const float* __restrict__ b,
    int warp, int lane)
{
    const int mb = warp >> 2;
    const int rbase = (warp & 3) * 4;
    const int kbl = lane >> 3;
    const int coff = (lane & 3) * 4 + 2 * ((lane >> 2) & 1);
#pragma unroll
    for (int rr = 0; rr < 4; rr++) {
        const int r16 = rbase + rr;
        const int wb = (r16 & 7) * 16 + ((r16 >> 3) & 1) + coff;
        float v[8], s = 0.f, q = 0.f;
#pragma unroll
        for (int j = 0; j < 8; j++) {
            float x = A[a_word(mb, kbl + 4 * j) + wb];
            v[j] = x; s += x; q += x * x;
        }
#pragma unroll
        for (int o = 16; o; o >>= 1) {
            s += __shfl_xor_sync(~0u, s, o);
            q += __shfl_xor_sync(~0u, q, o);
        }
        float mu = s * (1.f / 256.f);
        float var = fmaf(-mu, mu, q * (1.f / 256.f));
        float rs = rsqrtf(var + 1e-5f);
#pragma unroll
        for (int j = 0; j < 8; j++) {
            int c = lane + 32 * j;
            A[a_word(mb, kbl + 4 * j) + wb] =
                f2tf(fmaxf(fmaf((v[j] - mu) * rs, g[c], b[c]), 0.f));
        }
    }
}

}  // namespace

// pack weights into [kb][nb][64] frag blocks (tf32); also detect batch dtype
__global__ void prep_weights(const float* __restrict__ W1, const float* __restrict__ W2,
                             const float* __restrict__ W3, const int* __restrict__ b32) {
    if (blockIdx.x == 0 && threadIdx.x < 32) {
        int bad = (b32[2 * threadIdx.x + 1] != 0);
        unsigned m = __ballot_sync(~0u, bad);
        if (threadIdx.x == 0) g_is64 = (m == 0);
    }
    int id = blockIdx.x * 256 + threadIdx.x;
    if (id >= 180224) return;
    const float* W; int t, ncols, nbshift;
    if (id < W2B)      { W = W1; t = id;       ncols = 256; nbshift = 11; }
    else if (id < W3B) { W = W2; t = id - W2B; ncols = 256; nbshift = 11; }
    else               { W = W3; t = id - W3B; ncols = 64;  nbshift = 9;  }
    int kb = t >> nbshift;
    int nb = (t >> 6) & ((1 << (nbshift - 6)) - 1);
    int j = t & 63, l = j >> 1, p = j & 1;
    int k = kb * 8 + (l & 3) + p * 4;
    int n = nb * 8 + (l >> 2);
    g_wt[id] = f2tf(W[k * ncols + n]);
}

__global__ void __launch_bounds__(THREADS, 1)
fused_edge_kernel(const float* __restrict__ src, const float* __restrict__ dst_,
                  const float* __restrict__ ea, const float* __restrict__ u,
                  const void* __restrict__ braw, const float* __restrict__ wind,
                  const float* __restrict__ bw, const float* __restrict__ gw,
                  const float* __restrict__ btw, const float* __restrict__ Ww,
                  const float* __restrict__ b1, const float* __restrict__ g1,
                  const float* __restrict__ bt1, const float* __restrict__ b2,
                  const float* __restrict__ g2, const float* __restrict__ bt2,
                  const float* __restrict__ b3, float* __restrict__ out, int E)
{
    extern __shared__ float sm[];
    float* As = sm + A_OFF;
    float* P  = sm + P_OFF;
    int* bsm  = (int*)(sm + BSM_OFF);

    const int tid = threadIdx.x;
    const int warp = tid >> 5, lane = tid & 31;
    const int gid = lane >> 2, tig = lane & 3;
    const int e0 = blockIdx.x * ROWS;
    const int is64 = g_is64;

    if (tid < 256) {
        P[PWw + tid] = Ww[tid];
        P[Pb1 + tid] = b1[tid]; P[Pg1 + tid] = g1[tid]; P[Pt1 + tid] = bt1[tid];
        P[Pb2 + tid] = b2[tid]; P[Pg2 + tid] = g2[tid]; P[Pt2 + tid] = bt2[tid];
        if (tid < 128) { P[Pbw + tid] = bw[tid]; P[Pgw + tid] = gw[tid]; P[Ptw + tid] = btw[tid]; }
        if (tid < 64) {
            P[Pb3 + tid] = b3[tid];
            int e = e0 + tid;
            bsm[tid] = (e < E) ? (is64 ? (int)((const long long*)braw)[e]
                                       : ((const int*)braw)[e]) : 0;
        }
    }
    __syncthreads();

    // stage x: src|dest|ea|u[batch] -> frag-packed A cols 0..255 (tf32)
#pragma unroll 1
    for (int idx = tid; idx < ROWS * 16; idx += THREADS) {
        int r = idx >> 4, c4 = (idx & 15) * 4;
        int e = e0 + r;
        float4 vv[4];
        vv[0] = vv[1] = vv[2] = vv[3] = make_float4(0.f, 0.f, 0.f, 0.f);
        if (e < E) {
            size_t o = (size_t)e * 64 + c4;
            vv[0] = *(const float4*)(src + o);
            vv[1] = *(const float4*)(dst_ + o);
            vv[2] = *(const float4*)(ea + o);
        }
        vv[3] = *(const float4*)(u + (size_t)bsm[r] * 64 + c4);
        const int mb = r >> 4, gd = r & 7, hir = (r >> 3) & 1;
        const int hic = (c4 >> 2) & 1, kbq = c4 >> 3;
        const int wb = gd * 16 + hir + 2 * hic;
#pragma unroll
        for (int reg = 0; reg < 4; reg++) {
            int w = a_word(mb, reg * 8 + kbq) + wb;
            const float* vp = &vv[reg].x;
            As[w]      = f2tf(vp[0]);
            As[w + 4]  = f2tf(vp[1]);
            As[w + 8]  = f2tf(vp[2]);
            As[w + 12] = f2tf(vp[3]);
        }
    }
    __syncthreads();   // A published

    const int mb0 = warp >> 2;             // 0..3
    const int nb0 = (warp & 3) * 8;        // 0,8,16,24

    float acc[8][4];
#pragma unroll
    for (int nt = 0; nt < 8; nt++)
#pragma unroll
        for (int j = 0; j < 4; j++) acc[nt][j] = 0.f;

    // GEMM1 pass 1: x[:,0:256] @ W1 kb 0..31
    gemm_ldg<8>(g_wt, 32, 2048, As, acc, mb0, nb0, lane);

    __syncthreads();   // pass-1 A reads done before overwriting kb 0..15

    // winding MLP -> frag-packed A cols 0..127 (4 rows per warp)
    {
        int r = warp * 4;   // 4 consecutive rows
#pragma unroll
        for (int rr = 0; rr < 4; rr++, r = warp * 4 + rr) {
            int e = e0 + r;
            float w0 = 0.f, w1 = 0.f;
            if (e < E) { w0 = wind[(size_t)e * 2]; w1 = wind[(size_t)e * 2 + 1]; }
            float v[4], s = 0.f, q = 0.f;
#pragma unroll
            for (int j = 0; j < 4; j++) {
                int c = lane * 4 + j;
                float x = fmaf(w0, P[PWw + c], fmaf(w1, P[PWw + 128 + c], P[Pbw + c]));
                v[j] = x; s += x; q += x * x;
            }
#pragma unroll
            for (int o = 16; o; o >>= 1) {
                s += __shfl_xor_sync(~0u, s, o);
                q += __shfl_xor_sync(~0u, q, o);
            }
            float mu = s * (1.f / 128.f);
            float var = fmaf(-mu, mu, q * (1.f / 128.f));
            float rs = rsqrtf(var + 1e-5f);
            const int mb = r >> 4, gd = r & 7, hir = (r >> 3) & 1;
            const int kb = lane >> 1, hic = lane & 1;
            const int w = a_word(mb, kb) + gd * 16 + hir + 2 * hic;
#pragma unroll
            for (int j = 0; j < 4; j++) {
                int c = lane * 4 + j;
                As[w + j * 4] =
                    f2tf(fmaxf(fmaf((v[j] - mu) * rs, P[Pgw + c], P[Ptw + c]), 0.f));
            }
        }
    }
    __syncthreads();

    // GEMM1 pass 2: w @ W1 kb 32..47 (accumulate)
    gemm_ldg<8>(g_wt + 32 * 2048, 16, 2048, As, acc, mb0, nb0, lane);

    __syncthreads();
    store_acc_frag<8>(As, acc, P + Pb1, mb0, nb0, gid, tig);
    __syncthreads();
    ln_relu_frag(As, P + Pg1, P + Pt1, warp, lane);
    __syncthreads();

    // GEMM2
#pragma unroll
    for (int nt = 0; nt < 8; nt++)
#pragma unroll
        for (int j = 0; j < 4; j++) acc[nt][j] = 0.f;
    gemm_ldg<8>(g_wt + W2B, 32, 2048, As, acc, mb0, nb0, lane);

    __syncthreads();
    store_acc_frag<8>(As, acc, P + Pb2, mb0, nb0, gid, tig);
    __syncthreads();
    ln_relu_frag(As, P + Pg2, P + Pt2, warp, lane);
    __syncthreads();

    // GEMM3 (N=64): nb0 = (warp&3)*2, NT=2
    float acc3[2][4];
#pragma unroll
    for (int nt = 0; nt < 2; nt++)
#pragma unroll
        for (int j = 0; j < 4; j++) acc3[nt][j] = 0.f;
    const int nb03 = (warp & 3) * 2;
    gemm_ldg<2>(g_wt + W3B, 32, 512, As, acc3, mb0, nb03, lane);

    // epilogue: +b3, store
#pragma unroll
    for (int nt = 0; nt < 2; nt++) {
        int r0 = mb0 * 16 + gid;
        int c0 = (nb03 + nt) * 8 + 2 * tig;
        int e = e0 + r0;
        if (e < E)
            *(float2*)(out + (size_t)e * 64 + c0) =
                make_float2(acc3[nt][0] + P[Pb3 + c0],
                            acc3[nt][1] + P[Pb3 + c0 + 1]);
        e = e0 + r0 + 8;
        if (e < E)
            *(float2*)(out + (size_t)e * 64 + c0) =
                make_float2(acc3[nt][2] + P[Pb3 + c0],
                            acc3[nt][3] + P[Pb3 + c0 + 1]);
    }
}

extern "C" void kernel_launch(void* const* d_in, const int* in_sizes, int n_in,
                              void* d_out, int out_size)
{
    const float* src = (const float*)d_in[0];
    const float* dst_ = (const float*)d_in[1];
    const float* ea = (const float*)d_in[2];
    const float* u = (const float*)d_in[3];
    const void* batch = d_in[4];
    const float* wind = (const float*)d_in[5];
    const float* Ww = (const float*)d_in[6];
    const float* bw = (const float*)d_in[7];
    const float* gw = (const float*)d_in[8];
    const float* btw = (const float*)d_in[9];
    const float* W1 = (const float*)d_in[10];
    const float* b1 = (const float*)d_in[11];
    const float* g1 = (const float*)d_in[12];
    const float* bt1 = (const float*)d_in[13];
    const float* W2 = (const float*)d_in[14];
    const float* b2 = (const float*)d_in[15];
    const float* g2 = (const float*)d_in[16];
    const float* bt2 = (const float*)d_in[17];
    const float* W3 = (const float*)d_in[18];
    const float* b3 = (const float*)d_in[19];
    const int E = in_sizes[0] / 64;

    cudaFuncSetAttribute(fused_edge_kernel,
                         cudaFuncAttributeMaxDynamicSharedMemorySize, SMEM_BYTES);

    prep_weights<<<704, 256>>>(W1, W2, W3, (const int*)batch);

    fused_edge_kernel<<<(E + ROWS - 1) / ROWS, THREADS, SMEM_BYTES>>>(
        src, dst_, ea, u, batch, wind,
        bw, gw, btw, Ww,
        b1, g1, bt1, b2, g2, bt2, b3, (float*)d_out, E);
}

// round 9
// speedup vs baseline: 1.3014x; 1.3014x over previous
#include <cuda_runtime.h>
#include <cstdint>

namespace {

constexpr int ROWS = 64;           // edges per CTA
constexpr int BLKW = 132;          // words per A frag block (512B + 16B pad)
constexpr int A_OFF = 0;           // 4 mb x 32 kb blocks = 16896 floats
constexpr int P_OFF = 16896;       // 2240 params
constexpr int BSM_OFF = 19136;     // 64 batch ids
constexpr int SMF = 19200;
constexpr int SMEM_BYTES = SMF * 4;   // 76800 B -> 2 CTAs/SM

constexpr int Pb1 = 0, Pg1 = 256, Pt1 = 512, Pb2 = 768, Pg2 = 1024, Pt2 = 1280;
constexpr int Pb3 = 1536, PWw = 1600, Pbw = 1856, Pgw = 1984, Ptw = 2112;

// frag-packed tf32 weights: [kb][nb][64]; W1 48x32, W2 32x32, W3 32x8
constexpr int W2B = 98304, W3B = 163840;
__device__ float g_wt[180224];
__device__ int g_is64;

__device__ __forceinline__ float f2tf(float f) {
    unsigned u; asm("cvt.rna.tf32.f32 %0, %1;" : "=r"(u) : "f"(f));
    return __uint_as_float(u);
}
__device__ __forceinline__ void mma8(float* d, const unsigned* a, unsigned b0, unsigned b1) {
    asm volatile(
        "mma.sync.aligned.m16n8k8.row.col.f32.tf32.tf32.f32 "
        "{%0,%1,%2,%3},{%4,%5,%6,%7},{%8,%9},{%0,%1,%2,%3};\n"
        : "+f"(d[0]), "+f"(d[1]), "+f"(d[2]), "+f"(d[3])
        : "r"(a[0]), "r"(a[1]), "r"(a[2]), "r"(a[3]), "r"(b0), "r"(b1));
}
__device__ __forceinline__ int a_word(int mb, int kb) { return (mb * 32 + kb) * BLKW; }

template <int NT>
__device__ __forceinline__ void ldB(const float* __restrict__ Wb, int kb, int nbstride,
                                    int nb0, int lane, float2 (&br)[NT]) {
    const float* p = Wb + (size_t)kb * nbstride + nb0 * 64 + lane * 2;
#pragma unroll
    for (int nt = 0; nt < NT; nt++) br[nt] = *(const float2*)(p + nt * 64);
}
__device__ __forceinline__ void ldA(const float* __restrict__ As, int mb0, int kb,
                                    int lane, unsigned (&a)[2][4]) {
#pragma unroll
    for (int mt = 0; mt < 2; mt++) {
        float4 av = *(const float4*)(As + a_word(mb0 + mt, kb) + lane * 4);
        a[mt][0] = __float_as_uint(av.x); a[mt][1] = __float_as_uint(av.y);
        a[mt][2] = __float_as_uint(av.z); a[mt][3] = __float_as_uint(av.w);
    }
}
template <int NT>
__device__ __forceinline__ void kstep(const unsigned (&a)[2][4], const float2 (&br)[NT],
                                      float (&acc)[2][NT][4]) {
#pragma unroll
    for (int nt = 0; nt < NT; nt++) {
        unsigned b0 = __float_as_uint(br[nt].x), b1 = __float_as_uint(br[nt].y);
        mma8(acc[0][nt], a[0], b0, b1);
        mma8(acc[1][nt], a[1], b0, b1);
    }
}

// Barrier-free GEMM: A frag-packed smem, B frag-packed gmem.
// BOTH operands software-pipelined one kstep ahead (unroll-by-2 ping-pong).
// KB must be even.
template <int NT>
__device__ __forceinline__ void gemm_ldg(
    const float* __restrict__ Wb, const int KB, const int nbstride,
    const float* __restrict__ As, float (&acc)[2][NT][4],
    const int nb0, const int warp, const int lane)
{
    const int mb0 = (warp >> 2) * 2;
    float2 b0[NT], b1[NT];
    unsigned a0[2][4], a1[2][4];
    ldB<NT>(Wb, 0, nbstride, nb0, lane, b0);
    ldA(As, mb0, 0, lane, a0);
#pragma unroll 1
    for (int kb = 0; kb < KB; kb += 2) {
        ldB<NT>(Wb, kb + 1, nbstride, nb0, lane, b1);
        ldA(As, mb0, kb + 1, lane, a1);
        kstep<NT>(a0, b0, acc);
        const int kn = (kb + 2 < KB) ? kb + 2 : 0;   // clamped dummy on last iter
        ldB<NT>(Wb, kn, nbstride, nb0, lane, b0);
        ldA(As, mb0, kn, lane, a0);
        kstep<NT>(a1, b1, acc);
    }
}

template <int MT, int NT>
__device__ __forceinline__ void store_acc_frag(
    float* __restrict__ A, const float (&acc)[MT][NT][4], const float* __restrict__ bias,
    int mb0, int nb0, int gid, int tig)
{
    const int base = gid * 16 + (tig & 1) * 8 + 2 * (tig >> 1);
#pragma unroll
    for (int mt = 0; mt < MT; mt++)
#pragma unroll
        for (int nt = 0; nt < NT; nt++) {
            int c0 = (nb0 + nt) * 8 + 2 * tig;
            int w = a_word(mb0 + mt, nb0 + nt) + base;
            A[w]     = acc[mt][nt][0] + bias[c0];
            A[w + 4] = acc[mt][nt][1] + bias[c0 + 1];
            A[w + 1] = acc[mt][nt][2] + bias[c0];
            A[w + 5] = acc[mt][nt][3] + bias[c0 + 1];
        }
}

// in-place LN+ReLU over 256-wide rows of frag-packed A; 8 warps x 8 rows; tf32 out
__device__ __forceinline__ void ln_relu_frag(
    float* __restrict__ A, const float* __restrict__ g, const float* __restrict__ b,
    int warp, int lane)
{
    const int mb = warp >> 1, hir = warp & 1;
    const int off = (lane & 3) * 4 + hir + 2 * ((lane >> 2) & 1);
    const int kbl = lane >> 3;
#pragma unroll 1
    for (int rr = 0; rr < 8; rr++) {
        const int wb = rr * 16 + off;
        float v[8], s = 0.f, q = 0.f;
#pragma unroll
        for (int j = 0; j < 8; j++) {
            float x = A[a_word(mb, kbl + 4 * j) + wb];
            v[j] = x; s += x; q += x * x;
        }
#pragma unroll
        for (int o = 16; o; o >>= 1) {
            s += __shfl_xor_sync(~0u, s, o);
            q += __shfl_xor_sync(~0u, q, o);
        }
        float mu = s * (1.f / 256.f);
        float var = fmaf(-mu, mu, q * (1.f / 256.f));
        float rs = rsqrtf(var + 1e-5f);
#pragma unroll
        for (int j = 0; j < 8; j++) {
            int c = lane + 32 * j;
            A[a_word(mb, kbl + 4 * j) + wb] =
                f2tf(fmaxf(fmaf((v[j] - mu) * rs, g[c], b[c]), 0.f));
        }
    }
}

}  // namespace

// pack weights into [kb][nb][64] frag blocks (tf32); also detect batch dtype
__global__ void prep_weights(const float* __restrict__ W1, const float* __restrict__ W2,
                             const float* __restrict__ W3, const int* __restrict__ b32) {
    if (blockIdx.x == 0 && threadIdx.x < 32) {
        int bad = (b32[2 * threadIdx.x + 1] != 0);
        unsigned m = __ballot_sync(~0u, bad);
        if (threadIdx.x == 0) g_is64 = (m == 0);
    }
    int id = blockIdx.x * 256 + threadIdx.x;
    if (id >= 180224) return;
    const float* W; int t, ncols, nbshift;
    if (id < W2B)      { W = W1; t = id;       ncols = 256; nbshift = 11; }
    else if (id < W3B) { W = W2; t = id - W2B; ncols = 256; nbshift = 11; }
    else               { W = W3; t = id - W3B; ncols = 64;  nbshift = 9;  }
    int kb = t >> nbshift;
    int nb = (t >> 6) & ((1 << (nbshift - 6)) - 1);
    int j = t & 63, l = j >> 1, p = j & 1;
    int k = kb * 8 + (l & 3) + p * 4;
    int n = nb * 8 + (l >> 2);
    g_wt[id] = f2tf(W[k * ncols + n]);
}

__global__ void __launch_bounds__(256, 2)
fused_edge_kernel(const float* __restrict__ src, const float* __restrict__ dst_,
                  const float* __restrict__ ea, const float* __restrict__ u,
                  const void* __restrict__ braw, const float* __restrict__ wind,
                  const float* __restrict__ bw, const float* __restrict__ gw,
                  const float* __restrict__ btw, const float* __restrict__ Ww,
                  const float* __restrict__ b1, const float* __restrict__ g1,
                  const float* __restrict__ bt1, const float* __restrict__ b2,
                  const float* __restrict__ g2, const float* __restrict__ bt2,
                  const float* __restrict__ b3, float* __restrict__ out, int E)
{
    extern __shared__ float sm[];
    float* As = sm + A_OFF;
    float* P  = sm + P_OFF;
    int* bsm  = (int*)(sm + BSM_OFF);

    const int tid = threadIdx.x;
    const int warp = tid >> 5, lane = tid & 31;
    const int gid = lane >> 2, tig = lane & 3;
    const int e0 = blockIdx.x * ROWS;
    const int is64 = g_is64;

    if (tid < 256) {
        P[PWw + tid] = Ww[tid];
        P[Pb1 + tid] = b1[tid]; P[Pg1 + tid] = g1[tid]; P[Pt1 + tid] = bt1[tid];
        P[Pb2 + tid] = b2[tid]; P[Pg2 + tid] = g2[tid]; P[Pt2 + tid] = bt2[tid];
        if (tid < 128) { P[Pbw + tid] = bw[tid]; P[Pgw + tid] = gw[tid]; P[Ptw + tid] = btw[tid]; }
        if (tid < 64) {
            P[Pb3 + tid] = b3[tid];
            int e = e0 + tid;
            bsm[tid] = (e < E) ? (is64 ? (int)((const long long*)braw)[e]
                                       : ((const int*)braw)[e]) : 0;
        }
    }
    __syncthreads();

    // stage x: src|dest|ea|u[batch] -> frag-packed A cols 0..255 (tf32)
#pragma unroll 1
    for (int idx = tid; idx < ROWS * 16; idx += 256) {
        int r = idx >> 4, c4 = (idx & 15) * 4;
        int e = e0 + r;
        float4 vv[4];
        vv[0] = vv[1] = vv[2] = vv[3] = make_float4(0.f, 0.f, 0.f, 0.f);
        if (e < E) {
            size_t o = (size_t)e * 64 + c4;
            vv[0] = *(const float4*)(src + o);
            vv[1] = *(const float4*)(dst_ + o);
            vv[2] = *(const float4*)(ea + o);
        }
        vv[3] = *(const float4*)(u + (size_t)bsm[r] * 64 + c4);
        const int mb = r >> 4, gd = r & 7, hir = (r >> 3) & 1;
        const int hic = (c4 >> 2) & 1, kbq = c4 >> 3;
        const int wb = gd * 16 + hir + 2 * hic;
#pragma unroll
        for (int reg = 0; reg < 4; reg++) {
            int w = a_word(mb, reg * 8 + kbq) + wb;
            const float* vp = &vv[reg].x;
            As[w]      = f2tf(vp[0]);
            As[w + 4]  = f2tf(vp[1]);
            As[w + 8]  = f2tf(vp[2]);
            As[w + 12] = f2tf(vp[3]);
        }
    }
    __syncthreads();   // A published

    const int mb0 = (warp >> 2) * 2;
    const int nb0 = (warp & 3) * 8;

    float acc[2][8][4];
#pragma unroll
    for (int mt = 0; mt < 2; mt++)
#pragma unroll
        for (int nt = 0; nt < 8; nt++)
#pragma unroll
            for (int j = 0; j < 4; j++) acc[mt][nt][j] = 0.f;

    // GEMM1 pass 1: x[:,0:256] @ W1 kb 0..31 (barrier-free)
    gemm_ldg<8>(g_wt, 32, 2048, As, acc, nb0, warp, lane);

    __syncthreads();   // pass-1 A reads done before overwriting kb 0..15

    // winding MLP -> frag-packed A cols 0..127
#pragma unroll 1
    for (int rr = 0; rr < 8; rr++) {
        int r = warp * 8 + rr, e = e0 + r;
        float w0 = 0.f, w1 = 0.f;
        if (e < E) { w0 = wind[(size_t)e * 2]; w1 = wind[(size_t)e * 2 + 1]; }
        float v[4], s = 0.f, q = 0.f;
#pragma unroll
        for (int j = 0; j < 4; j++) {
            int c = lane * 4 + j;
            float x = fmaf(w0, P[PWw + c], fmaf(w1, P[PWw + 128 + c], P[Pbw + c]));
            v[j] = x; s += x; q += x * x;
        }
#pragma unroll
        for (int o = 16; o; o >>= 1) {
            s += __shfl_xor_sync(~0u, s, o);
            q += __shfl_xor_sync(~0u, q, o);
        }
        float mu = s * (1.f / 128.f);
        float var = fmaf(-mu, mu, q * (1.f / 128.f));
        float rs = rsqrtf(var + 1e-5f);
        const int mb = r >> 4, gd = r & 7, hir = (r >> 3) & 1;
        const int kb = lane >> 1, hic = lane & 1;
        const int w = a_word(mb, kb) + gd * 16 + hir + 2 * hic;
#pragma unroll
        for (int j = 0; j < 4; j++) {
            int c = lane * 4 + j;
            As[w + j * 4] = f2tf(fmaxf(fmaf((v[j] - mu) * rs, P[Pgw + c], P[Ptw + c]), 0.f));
        }
    }
    __syncthreads();

    // GEMM1 pass 2: w @ W1 kb 32..47 (accumulate)
    gemm_ldg<8>(g_wt + 32 * 2048, 16, 2048, As, acc, nb0, warp, lane);

    __syncthreads();
    store_acc_frag<2, 8>(As, acc, P + Pb1, mb0, nb0, gid, tig);
    __syncthreads();
    ln_relu_frag(As, P + Pg1, P + Pt1, warp, lane);
    __syncthreads();

    // GEMM2
#pragma unroll
    for (int mt = 0; mt < 2; mt++)
#pragma unroll
        for (int nt = 0; nt < 8; nt++)
#pragma unroll
            for (int j = 0; j < 4; j++) acc[mt][nt][j] = 0.f;
    gemm_ldg<8>(g_wt + W2B, 32, 2048, As, acc, nb0, warp, lane);

    __syncthreads();
    store_acc_frag<2, 8>(As, acc, P + Pb2, mb0, nb0, gid, tig);
    __syncthreads();
    ln_relu_frag(As, P + Pg2, P + Pt2, warp, lane);
    __syncthreads();

    // GEMM3 (N=64)
    float acc3[2][2][4];
#pragma unroll
    for (int mt = 0; mt < 2; mt++)
#pragma unroll
        for (int nt = 0; nt < 2; nt++)
#pragma unroll
            for (int j = 0; j < 4; j++) acc3[mt][nt][j] = 0.f;
    const int nb03 = (warp & 3) * 2;
    gemm_ldg<2>(g_wt + W3B, 32, 512, As, acc3, nb03, warp, lane);

#pragma unroll
    for (int mt = 0; mt < 2; mt++)
#pragma unroll
        for (int nt = 0; nt < 2; nt++) {
            int r0 = (warp >> 2) * 32 + mt * 16 + gid;
            int c0 = (nb03 + nt) * 8 + 2 * tig;
            int e = e0 + r0;
            if (e < E)
                *(float2*)(out + (size_t)e * 64 + c0) =
                    make_float2(acc3[mt][nt][0] + P[Pb3 + c0],
                                acc3[mt][nt][1] + P[Pb3 + c0 + 1]);
            e = e0 + r0 + 8;
            if (e < E)
                *(float2*)(out + (size_t)e * 64 + c0) =
                    make_float2(acc3[mt][nt][2] + P[Pb3 + c0],
                                acc3[mt][nt][3] + P[Pb3 + c0 + 1]);
        }
}

extern "C" void kernel_launch(void* const* d_in, const int* in_sizes, int n_in,
                              void* d_out, int out_size)
{
    const float* src = (const float*)d_in[0];
    const float* dst_ = (const float*)d_in[1];
    const float* ea = (const float*)d_in[2];
    const float* u = (const float*)d_in[3];
    const void* batch = d_in[4];
    const float* wind = (const float*)d_in[5];
    const float* Ww = (const float*)d_in[6];
    const float* bw = (const float*)d_in[7];
    const float* gw = (const float*)d_in[8];
    const float* btw = (const float*)d_in[9];
    const float* W1 = (const float*)d_in[10];
    const float* b1 = (const float*)d_in[11];
    const float* g1 = (const float*)d_in[12];
    const float* bt1 = (const float*)d_in[13];
    const float* W2 = (const float*)d_in[14];
    const float* b2 = (const float*)d_in[15];
    const float* g2 = (const float*)d_in[16];
    const float* bt2 = (const float*)d_in[17];
    const float* W3 = (const float*)d_in[18];
    const float* b3 = (const float*)d_in[19];
    const int E = in_sizes[0] / 64;

    cudaFuncSetAttribute(fused_edge_kernel,
                         cudaFuncAttributeMaxDynamicSharedMemorySize, SMEM_BYTES);

    prep_weights<<<704, 256>>>(W1, W2, W3, (const int*)batch);

    fused_edge_kernel<<<(E + ROWS - 1) / ROWS, 256, SMEM_BYTES>>>(
        src, dst_, ea, u, batch, wind,
        bw, gw, btw, Ww,
        b1, g1, bt1, b2, g2, bt2, b3, (float*)d_out, E);
}